// round 9
// baseline (speedup 1.0000x reference)
#include <cuda_runtime.h>

// FINAL configuration (Round-4 body; best observed sample 4.544us, identical
// binary re-measured at 4.832us -> run-to-run spread ±0.29us, so all R2-R8
// body variants are statistically equivalent; this one has the best sample
// and the shortest modeled critical path).
//
// out[k] = sum_d x[d] * S[d][k],  S[d][k] = sum_n M[n][d][k].
// M flattened to 400 float4 rows (row p = (n,d), comps = k). Single warp;
// lane t owns rows p = t + 32j; since 32 % 4 == 0, d = t & 3 is fixed per
// lane so the x scalar is loop-invariant.
//
// x load issued first; accumulation is x-free (pure FADDs, dual accumulators
// to halve the chain) so x's L2 latency overlaps it; one FMUL per component
// applies x[d]. 400 = 32*12 + 16: 12 unconditional float4 loads + one
// predicated tail (lanes 0..15).
//
// Reduction: 6 SHFLs, depth 5 (f32 REDUX is rejected by ptxas on sm_103):
//   stage xor 1: fold 4 comps -> 2   (2 parallel SHFLs)
//   stage xor 2: fold 2 comps -> 1   (1 SHFL)
//   stages xor 4,8,16: scalar butterfly (3 SHFLs)
// Lane t<4 stores out[k], k = 2*(t&1) + ((t>>1)&1).

__global__ void __launch_bounds__(32, 1)
bigfanout_kernel(const float* __restrict__ x,
                 const float* __restrict__ matrices,
                 float* __restrict__ out) {
    const int t = threadIdx.x;            // 0..31
    const float xv = x[t & 3];            // issued early; consumed late

    const float4* __restrict__ rows = reinterpret_cast<const float4*>(matrices);

    // Pure-add accumulation, dual accumulators to halve the FADD chain.
    float e0 = 0.f, e1 = 0.f, e2 = 0.f, e3 = 0.f;
    float o0 = 0.f, o1 = 0.f, o2 = 0.f, o3 = 0.f;

    #pragma unroll
    for (int j = 0; j < 12; j += 2) {
        float4 re = rows[t + 32 * j];
        float4 ro = rows[t + 32 * (j + 1)];
        e0 += re.x;  e1 += re.y;  e2 += re.z;  e3 += re.w;
        o0 += ro.x;  o1 += ro.y;  o2 += ro.z;  o3 += ro.w;
    }

    // Tail: rows 384..399, lanes 0..15. 384 % 4 == 0 so d = t&3 still holds.
    if (t < 16) {
        float4 r = rows[384 + t];
        e0 += r.x;  e1 += r.y;  e2 += r.z;  e3 += r.w;
    }

    // Apply x[d] once per component (first and only consumer of the x load).
    float v0 = (e0 + o0) * xv;
    float v1 = (e1 + o1) * xv;
    float v2 = (e2 + o2) * xv;
    float v3 = (e3 + o3) * xv;

    const unsigned FULL = 0xFFFFFFFFu;

    // Stage xor 1: even lanes keep comps {0,1}, odd lanes keep {2,3}.
    {
        bool hi = (t & 1);
        float s0 = hi ? v0 : v2;          // send what the partner keeps
        float s1 = hi ? v1 : v3;
        float r0 = __shfl_xor_sync(FULL, s0, 1);
        float r1 = __shfl_xor_sync(FULL, s1, 1);
        float k0 = hi ? v2 : v0;
        float k1 = hi ? v3 : v1;
        v0 = k0 + r0;
        v1 = k1 + r1;
    }

    // Stage xor 2: keep one component per lane.
    float w;
    {
        bool hi = (t & 2);
        float s = hi ? v0 : v1;
        float r = __shfl_xor_sync(FULL, s, 2);
        float k = hi ? v1 : v0;
        w = k + r;
    }

    // Scalar butterfly over remaining lane bits (8 lanes share t&3).
    w += __shfl_xor_sync(FULL, w, 4);
    w += __shfl_xor_sync(FULL, w, 8);
    w += __shfl_xor_sync(FULL, w, 16);

    // Lane t (<4) holds component k = 2*(t&1) + ((t>>1)&1).
    if (t < 4) {
        int k = ((t & 1) << 1) | ((t >> 1) & 1);
        out[k] = w;
    }
}

extern "C" void kernel_launch(void* const* d_in, const int* in_sizes, int n_in,
                              void* d_out, int out_size) {
    const float* x        = (const float*)d_in[0];   // [1,4] float32
    const float* matrices = (const float*)d_in[1];   // [100,4,4] float32
    float* out            = (float*)d_out;           // [4] float32

    bigfanout_kernel<<<1, 32>>>(x, matrices, out);
}

// round 10
// speedup vs baseline: 1.0709x; 1.0709x over previous
#include <cuda_runtime.h>

// FINAL configuration (Round-4 body). Identical-binary measurements: 4.544,
// 4.832, 4.832 us -> run-to-run spread dominates all body variants tested
// (R2-R8, 4.54-4.83us). Kernel body is ~0.4us of a ~4.7us replay; the rest
// is graph-replay dispatch + launch/teardown + one L2 round trip (L1 is
// flushed per launch on Blackwell), none of it addressable from this file.
//
// out[k] = sum_d x[d] * S[d][k],  S[d][k] = sum_n M[n][d][k].
// M flattened to 400 float4 rows (row p = (n,d), comps = k). Single warp;
// lane t owns rows p = t + 32j; since 32 % 4 == 0, d = t & 3 is fixed per
// lane so the x scalar is loop-invariant.
//
// x load issued first; accumulation is x-free (pure FADDs, dual accumulators
// to halve the chain) so x's L2 latency overlaps it; one FMUL per component
// applies x[d]. 400 = 32*12 + 16: 12 unconditional float4 loads + one
// predicated tail (lanes 0..15).
//
// Reduction: 6 SHFLs, depth 5 (f32 REDUX is rejected by ptxas on sm_103):
//   stage xor 1: fold 4 comps -> 2   (2 parallel SHFLs)
//   stage xor 2: fold 2 comps -> 1   (1 SHFL)
//   stages xor 4,8,16: scalar butterfly (3 SHFLs)
// Lane t<4 stores out[k], k = 2*(t&1) + ((t>>1)&1).

__global__ void __launch_bounds__(32, 1)
bigfanout_kernel(const float* __restrict__ x,
                 const float* __restrict__ matrices,
                 float* __restrict__ out) {
    const int t = threadIdx.x;            // 0..31
    const float xv = x[t & 3];            // issued early; consumed late

    const float4* __restrict__ rows = reinterpret_cast<const float4*>(matrices);

    // Pure-add accumulation, dual accumulators to halve the FADD chain.
    float e0 = 0.f, e1 = 0.f, e2 = 0.f, e3 = 0.f;
    float o0 = 0.f, o1 = 0.f, o2 = 0.f, o3 = 0.f;

    #pragma unroll
    for (int j = 0; j < 12; j += 2) {
        float4 re = rows[t + 32 * j];
        float4 ro = rows[t + 32 * (j + 1)];
        e0 += re.x;  e1 += re.y;  e2 += re.z;  e3 += re.w;
        o0 += ro.x;  o1 += ro.y;  o2 += ro.z;  o3 += ro.w;
    }

    // Tail: rows 384..399, lanes 0..15. 384 % 4 == 0 so d = t&3 still holds.
    if (t < 16) {
        float4 r = rows[384 + t];
        e0 += r.x;  e1 += r.y;  e2 += r.z;  e3 += r.w;
    }

    // Apply x[d] once per component (first and only consumer of the x load).
    float v0 = (e0 + o0) * xv;
    float v1 = (e1 + o1) * xv;
    float v2 = (e2 + o2) * xv;
    float v3 = (e3 + o3) * xv;

    const unsigned FULL = 0xFFFFFFFFu;

    // Stage xor 1: even lanes keep comps {0,1}, odd lanes keep {2,3}.
    {
        bool hi = (t & 1);
        float s0 = hi ? v0 : v2;          // send what the partner keeps
        float s1 = hi ? v1 : v3;
        float r0 = __shfl_xor_sync(FULL, s0, 1);
        float r1 = __shfl_xor_sync(FULL, s1, 1);
        float k0 = hi ? v2 : v0;
        float k1 = hi ? v3 : v1;
        v0 = k0 + r0;
        v1 = k1 + r1;
    }

    // Stage xor 2: keep one component per lane.
    float w;
    {
        bool hi = (t & 2);
        float s = hi ? v0 : v1;
        float r = __shfl_xor_sync(FULL, s, 2);
        float k = hi ? v1 : v0;
        w = k + r;
    }

    // Scalar butterfly over remaining lane bits (8 lanes share t&3).
    w += __shfl_xor_sync(FULL, w, 4);
    w += __shfl_xor_sync(FULL, w, 8);
    w += __shfl_xor_sync(FULL, w, 16);

    // Lane t (<4) holds component k = 2*(t&1) + ((t>>1)&1).
    if (t < 4) {
        int k = ((t & 1) << 1) | ((t >> 1) & 1);
        out[k] = w;
    }
}

extern "C" void kernel_launch(void* const* d_in, const int* in_sizes, int n_in,
                              void* d_out, int out_size) {
    const float* x        = (const float*)d_in[0];   // [1,4] float32
    const float* matrices = (const float*)d_in[1];   // [100,4,4] float32
    float* out            = (float*)d_out;           // [4] float32

    bigfanout_kernel<<<1, 32>>>(x, matrices, out);
}